// round 1
// baseline (speedup 1.0000x reference)
#include <cuda_runtime.h>
#include <math.h>

// Problem constants
#define NHIST 24
#define NFORE 20
#define HID   256
#define CAT   44        // NHIST + NFORE
#define MT    128       // rows per block
#define NTHREADS 512
#define CSTR  48        // sComb row stride (floats), mult of 4
#define ASTR  260       // sAct row stride (floats), mult of 4
#define W4STR 32        // padded width for final layer weights

// SMEM layout (floats):
//   sComb : MT*CSTR        = 6144
//   sAct  : MT*ASTR        = 33280
//   sW    : CAT*HID        = 11264  (reused as 32x256 tiles and 256x32 padded W4)
//   sB    : HID            = 256
#define SMEM_FLOATS (MT*CSTR + MT*ASTR + CAT*HID + HID)

__device__ __forceinline__ float sigmoidf_(float x) {
    return 1.0f / (1.0f + expf(-x));
}

// Compute an 8x8 register tile: acc += act[row0..row0+7][0..kCount) @ W[kCount x 256][col0..col0+7]
__device__ __forceinline__ void gemm_tile(const float* __restrict__ actBase, int actStride,
                                          const float* __restrict__ wBase,
                                          int kCount, int row0, int col0,
                                          float acc[8][8])
{
    for (int k = 0; k < kCount; k += 4) {
        float4 a4[8];
        #pragma unroll
        for (int i = 0; i < 8; i++)
            a4[i] = *(const float4*)&actBase[(row0 + i) * actStride + k];
        #pragma unroll
        for (int t = 0; t < 4; t++) {
            float4 wA = *(const float4*)&wBase[(k + t) * HID + col0];
            float4 wB = *(const float4*)&wBase[(k + t) * HID + col0 + 4];
            #pragma unroll
            for (int i = 0; i < 8; i++) {
                float av = (t == 0) ? a4[i].x : (t == 1) ? a4[i].y : (t == 2) ? a4[i].z : a4[i].w;
                acc[i][0] += av * wA.x;
                acc[i][1] += av * wA.y;
                acc[i][2] += av * wA.z;
                acc[i][3] += av * wA.w;
                acc[i][4] += av * wB.x;
                acc[i][5] += av * wB.y;
                acc[i][6] += av * wB.z;
                acc[i][7] += av * wB.w;
            }
        }
    }
}

__global__ void __launch_bounds__(NTHREADS, 1)
axiom_fused_kernel(const float* __restrict__ hist,
                   const float* __restrict__ w1, const float* __restrict__ b1,
                   const float* __restrict__ w2, const float* __restrict__ b2,
                   const float* __restrict__ w3, const float* __restrict__ b3,
                   const float* __restrict__ w4, const float* __restrict__ b4,
                   const float* __restrict__ p_alpha, const float* __restrict__ p_beta,
                   const float* __restrict__ p_gamma, const float* __restrict__ p_lam,
                   float* __restrict__ out, int B)
{
    extern __shared__ float smem[];
    float* sComb = smem;                    // [MT][CSTR]
    float* sAct  = sComb + MT * CSTR;       // [MT][ASTR]
    float* sW    = sAct  + MT * ASTR;       // CAT*HID floats
    float* sB    = sW    + CAT * HID;       // HID floats

    const int tid  = threadIdx.x;
    const int lane = tid & 31;
    const int wrp  = tid >> 5;              // 0..15
    const int row0 = wrp * 8;               // local row group
    const int col0 = lane * 8;              // column group
    const int gRow0 = blockIdx.x * MT;

    // ---------- phase 0: load history tile ----------
    for (int idx = tid; idx < MT * NHIST; idx += NTHREADS) {
        int r = idx / NHIST, c = idx % NHIST;
        sComb[r * CSTR + c] = hist[(size_t)(gRow0 + r) * NHIST + c];
    }
    __syncthreads();

    // ---------- phase 1: physics recurrence (one thread per row) ----------
    if (tid < MT) {
        const float a = sigmoidf_(p_alpha[0]);
        const float b = sigmoidf_(p_beta[0]);
        const float g = fabsf(p_gamma[0]);
        float* rowp = &sComb[tid * CSTR];
        float d0 = rowp[18], d1 = rowp[19], d2 = rowp[20];
        float d3 = rowp[21], d4 = rowp[22], d5 = rowp[23];
        float T = d5;
        #pragma unroll
        for (int i = 0; i < NFORE; i++) {
            float Tn = T - a * T - b * d0 - g * (T * T * T);
            d0 = d1; d1 = d2; d2 = d3; d3 = d4; d4 = d5; d5 = Tn;
            rowp[24 + i] = Tn;
            T = Tn;
        }
    }
    __syncthreads();

    // write T_physics to out[B*NFORE ...), coalesced
    for (int idx = tid; idx < MT * NFORE; idx += NTHREADS) {
        int r = idx / NFORE, c = idx % NFORE;
        out[(size_t)B * NFORE + (size_t)(gRow0 + r) * NFORE + c] = sComb[r * CSTR + 24 + c];
    }

    // ---------- phase 2: layer 1  h = tanh(combined @ w1 + b1) ----------
    {
        for (int idx = tid; idx < CAT * HID / 4; idx += NTHREADS)
            ((float4*)sW)[idx] = ((const float4*)w1)[idx];
        for (int idx = tid; idx < HID; idx += NTHREADS)
            sB[idx] = b1[idx];
        __syncthreads();

        float acc[8][8];
        #pragma unroll
        for (int i = 0; i < 8; i++)
            #pragma unroll
            for (int j = 0; j < 8; j++) acc[i][j] = 0.0f;

        gemm_tile(sComb, CSTR, sW, CAT, row0, col0, acc);

        __syncthreads();  // all reads of sW done before reuse; sAct write below is first use
        #pragma unroll
        for (int i = 0; i < 8; i++)
            #pragma unroll
            for (int j = 0; j < 8; j++)
                sAct[(row0 + i) * ASTR + col0 + j] = tanhf(acc[i][j] + sB[col0 + j]);
        __syncthreads();
    }

    // ---------- phases 3,4: two [256->256] tanh layers with K-tiled weights ----------
    const float* Ws[2] = {w2, w3};
    const float* Bs[2] = {b2, b3};
    for (int layer = 0; layer < 2; layer++) {
        const float* W = Ws[layer];
        float acc[8][8];
        #pragma unroll
        for (int i = 0; i < 8; i++)
            #pragma unroll
            for (int j = 0; j < 8; j++) acc[i][j] = 0.0f;

        for (int kt = 0; kt < HID / 32; kt++) {
            // previous tile fully consumed / sAct stable
            if (kt > 0) __syncthreads();
            for (int idx = tid; idx < 32 * HID / 4; idx += NTHREADS)
                ((float4*)sW)[idx] = ((const float4*)(W + kt * 32 * HID))[idx];
            if (kt == 0)
                for (int idx = tid; idx < HID; idx += NTHREADS) sB[idx] = Bs[layer][idx];
            __syncthreads();

            gemm_tile(sAct + kt * 32, ASTR, sW, 32, row0, col0, acc);
        }
        __syncthreads();  // everyone done reading sAct before overwrite
        #pragma unroll
        for (int i = 0; i < 8; i++)
            #pragma unroll
            for (int j = 0; j < 8; j++)
                sAct[(row0 + i) * ASTR + col0 + j] = tanhf(acc[i][j] + sB[col0 + j]);
        __syncthreads();
    }

    // ---------- phase 5: final layer  T_soft = c @ w4 + b4 ; outputs ----------
    {
        // load w4 [256,20] padded to stride 32 (zeros beyond col 20)
        for (int idx = tid; idx < HID * W4STR; idx += NTHREADS) {
            int k = idx >> 5, n = idx & 31;
            sW[idx] = (n < NFORE) ? w4[k * NFORE + n] : 0.0f;
        }
        __syncthreads();

        float acc8[8];
        #pragma unroll
        for (int i = 0; i < 8; i++) acc8[i] = 0.0f;

        for (int k = 0; k < HID; k += 4) {
            float w0 = sW[(k + 0) * W4STR + lane];
            float wv1 = sW[(k + 1) * W4STR + lane];
            float wv2 = sW[(k + 2) * W4STR + lane];
            float wv3 = sW[(k + 3) * W4STR + lane];
            #pragma unroll
            for (int i = 0; i < 8; i++) {
                float4 av = *(const float4*)&sAct[(row0 + i) * ASTR + k];
                acc8[i] += av.x * w0;
                acc8[i] += av.y * wv1;
                acc8[i] += av.z * wv2;
                acc8[i] += av.w * wv3;
            }
        }

        if (lane < NFORE) {
            const float bb  = b4[lane];
            const float lam = sigmoidf_(p_lam[0]);
            #pragma unroll
            for (int i = 0; i < 8; i++) {
                int gr = gRow0 + row0 + i;
                float ts = acc8[i] + bb;
                float tp = sComb[(row0 + i) * CSTR + 24 + lane] + lam * ts;
                out[(size_t)gr * NFORE + lane] = tp;                              // T_pred
                out[(size_t)2 * B * NFORE + (size_t)gr * NFORE + lane] = ts;      // T_soft
            }
        }
    }
}

extern "C" void kernel_launch(void* const* d_in, const int* in_sizes, int n_in,
                              void* d_out, int out_size)
{
    const float* hist  = (const float*)d_in[0];
    const float* w1    = (const float*)d_in[1];
    const float* b1    = (const float*)d_in[2];
    const float* w2    = (const float*)d_in[3];
    const float* b2    = (const float*)d_in[4];
    const float* w3    = (const float*)d_in[5];
    const float* b3    = (const float*)d_in[6];
    const float* w4    = (const float*)d_in[7];
    const float* b4    = (const float*)d_in[8];
    const float* alpha = (const float*)d_in[9];
    const float* beta  = (const float*)d_in[10];
    const float* gamma = (const float*)d_in[11];
    // d_in[12] = tau (unused)
    const float* lamx  = (const float*)d_in[13];
    float* out = (float*)d_out;

    const int B = in_sizes[0] / NHIST;
    const int nblocks = (B + MT - 1) / MT;
    const size_t smem_bytes = (size_t)SMEM_FLOATS * sizeof(float);

    cudaFuncSetAttribute(axiom_fused_kernel,
                         cudaFuncAttributeMaxDynamicSharedMemorySize,
                         (int)smem_bytes);

    axiom_fused_kernel<<<nblocks, NTHREADS, smem_bytes>>>(
        hist, w1, b1, w2, b2, w3, b3, w4, b4,
        alpha, beta, gamma, lamx, out, B);
}

// round 2
// speedup vs baseline: 1.1916x; 1.1916x over previous
#include <cuda_runtime.h>
#include <math.h>

// Problem constants
#define NHIST 24
#define NFORE 20
#define HID   256
#define CAT   44
#define MT    128       // rows per block
#define NTHREADS 512
#define CSTR  48        // sComb row stride
#define ASTR  260       // sAct row stride
#define W4STR 268       // transposed w4 row stride (268 % 32 = 12 -> conflict-free lanes)

// SMEM (floats): sComb 6144 | sAct 33280 | buf 2*8192 | sB 256
#define BUF_FLOATS 8192
#define SMEM_FLOATS (MT*CSTR + MT*ASTR + 2*BUF_FLOATS + 256)

typedef unsigned long long ull;

__device__ __forceinline__ ull fma2(ull a, ull b, ull c) {
    ull d; asm("fma.rn.f32x2 %0, %1, %2, %3;" : "=l"(d) : "l"(a), "l"(b), "l"(c)); return d;
}
__device__ __forceinline__ ull add2(ull a, ull b) {
    ull d; asm("add.rn.f32x2 %0, %1, %2;" : "=l"(d) : "l"(a), "l"(b)); return d;
}
__device__ __forceinline__ ull pack2(float a) {
    ull r; asm("mov.b64 %0, {%1, %1};" : "=l"(r) : "f"(a)); return r;
}
__device__ __forceinline__ void unpack2(ull v, float& lo, float& hi) {
    asm("mov.b64 {%0, %1}, %2;" : "=f"(lo), "=f"(hi) : "l"(v));
}
__device__ __forceinline__ float tanha(float x) {
    float r; asm("tanh.approx.f32 %0, %1;" : "=f"(r) : "f"(x)); return r;
}
__device__ __forceinline__ float sigmoidf_(float x) { return 1.0f / (1.0f + expf(-x)); }

// acc[i][j]: row i (row0+i), col pairs: j0=(4l,4l+1) j1=(4l+2,4l+3) j2=(128+4l,+1) j3=(128+4l+2,+3)
__device__ __forceinline__ void gemm_tile_p(const float* __restrict__ actBase, int astr,
                                            const float* __restrict__ wBase,
                                            int kCount, int row0, int lane,
                                            ull acc[8][4])
{
    const int c0 = 4 * lane;
    const int c1 = 128 + 4 * lane;
    for (int k = 0; k < kCount; k += 4) {
        float4 a4[8];
        #pragma unroll
        for (int i = 0; i < 8; i++)
            a4[i] = *(const float4*)&actBase[(row0 + i) * astr + k];
        #pragma unroll
        for (int t = 0; t < 4; t++) {
            ulonglong2 wA = *(const ulonglong2*)&wBase[(k + t) * HID + c0];
            ulonglong2 wB = *(const ulonglong2*)&wBase[(k + t) * HID + c1];
            #pragma unroll
            for (int i = 0; i < 8; i++) {
                float av = (t == 0) ? a4[i].x : (t == 1) ? a4[i].y : (t == 2) ? a4[i].z : a4[i].w;
                ull aa = pack2(av);
                acc[i][0] = fma2(aa, wA.x, acc[i][0]);
                acc[i][1] = fma2(aa, wA.y, acc[i][1]);
                acc[i][2] = fma2(aa, wB.x, acc[i][2]);
                acc[i][3] = fma2(aa, wB.y, acc[i][3]);
            }
        }
    }
}

__global__ void __launch_bounds__(NTHREADS, 1)
axiom_fused_kernel(const float* __restrict__ hist,
                   const float* __restrict__ w1, const float* __restrict__ b1,
                   const float* __restrict__ w2, const float* __restrict__ b2,
                   const float* __restrict__ w3, const float* __restrict__ b3,
                   const float* __restrict__ w4, const float* __restrict__ b4,
                   const float* __restrict__ p_alpha, const float* __restrict__ p_beta,
                   const float* __restrict__ p_gamma, const float* __restrict__ p_lam,
                   float* __restrict__ out, int B)
{
    extern __shared__ float smem[];
    float* sComb = smem;                    // [MT][CSTR]
    float* sAct  = sComb + MT * CSTR;       // [MT][ASTR]
    float* bufA  = sAct  + MT * ASTR;       // 8192
    float* bufB  = bufA  + BUF_FLOATS;      // 8192
    float* sB    = bufB  + BUF_FLOATS;      // 256
    const ull* sB2 = (const ull*)sB;

    const int tid  = threadIdx.x;
    const int lane = tid & 31;
    const int wrp  = tid >> 5;
    const int row0 = wrp * 8;
    const int gRow0 = blockIdx.x * MT;

    // ---------- phase 0: load history + w1 + b1 ----------
    for (int idx = tid; idx < MT * NHIST; idx += NTHREADS) {
        int r = idx / NHIST, c = idx % NHIST;
        sComb[r * CSTR + c] = hist[(size_t)(gRow0 + r) * NHIST + c];
    }
    for (int idx = tid; idx < CAT * HID / 4; idx += NTHREADS)
        ((float4*)bufA)[idx] = ((const float4*)w1)[idx];   // spans into bufB, fine
    if (tid < HID) sB[tid] = b1[tid];
    __syncthreads();

    // ---------- phase 1: physics ----------
    if (tid < MT) {
        const float a = sigmoidf_(p_alpha[0]);
        const float b = sigmoidf_(p_beta[0]);
        const float g = fabsf(p_gamma[0]);
        float* rowp = &sComb[tid * CSTR];
        float d0 = rowp[18], d1 = rowp[19], d2 = rowp[20];
        float d3 = rowp[21], d4 = rowp[22], d5 = rowp[23];
        float T = d5;
        #pragma unroll
        for (int i = 0; i < NFORE; i++) {
            float Tn = T - a * T - b * d0 - g * (T * T * T);
            d0 = d1; d1 = d2; d2 = d3; d3 = d4; d4 = d5; d5 = Tn;
            rowp[24 + i] = Tn;
            T = Tn;
        }
    }
    __syncthreads();

    // T_physics out (coalesced)
    for (int idx = tid; idx < MT * NFORE; idx += NTHREADS) {
        int r = idx / NFORE, c = idx % NFORE;
        out[(size_t)B * NFORE + (size_t)(gRow0 + r) * NFORE + c] = sComb[r * CSTR + 24 + c];
    }

    // ---------- layer 1: h = tanh(comb @ w1 + b1) ----------
    {
        ull acc[8][4];
        #pragma unroll
        for (int i = 0; i < 8; i++)
            #pragma unroll
            for (int j = 0; j < 4; j++) acc[i][j] = 0ULL;

        gemm_tile_p(sComb, CSTR, bufA, CAT, row0, lane, acc);

        // epilogue (writes sAct; no other reader of sAct yet -> no pre-sync)
        #pragma unroll
        for (int i = 0; i < 8; i++) {
            #pragma unroll
            for (int j = 0; j < 4; j++) {
                int cp = (j < 2) ? (4 * lane + 2 * j) : (128 + 4 * lane + 2 * (j - 2));
                ull v = add2(acc[i][j], sB2[cp >> 1]);
                float lo, hi; unpack2(v, lo, hi);
                float2 st; st.x = tanha(lo); st.y = tanha(hi);
                *(float2*)&sAct[(row0 + i) * ASTR + cp] = st;
            }
        }
        __syncthreads();   // sAct complete; bufA/bufB free
    }

    // ---------- layers 2,3: [256->256] tanh, K-tiled ping-pong ----------
    const float* Ws[2] = {w2, w3};
    const float* Bs[2] = {b2, b3};
    for (int layer = 0; layer < 2; layer++) {
        const float* W = Ws[layer];
        // preload tile 0 + bias
        #pragma unroll
        for (int t = 0; t < 4; t++)
            ((float4*)bufA)[tid + t * NTHREADS] = ((const float4*)W)[tid + t * NTHREADS];
        if (tid < HID) sB[tid] = Bs[layer][tid];
        __syncthreads();

        ull acc[8][4];
        #pragma unroll
        for (int i = 0; i < 8; i++)
            #pragma unroll
            for (int j = 0; j < 4; j++) acc[i][j] = 0ULL;

        float* bufs[2] = {bufA, bufB};
        int p = 0;
        for (int kt = 0; kt < 8; kt++) {
            float4 nxt0, nxt1, nxt2, nxt3;
            if (kt < 7) {
                const float4* src = (const float4*)(W + (kt + 1) * 32 * HID);
                nxt0 = src[tid];
                nxt1 = src[tid + NTHREADS];
                nxt2 = src[tid + 2 * NTHREADS];
                nxt3 = src[tid + 3 * NTHREADS];
            }
            gemm_tile_p(sAct + kt * 32, ASTR, bufs[p], 32, row0, lane, acc);
            if (kt < 7) {
                float4* dst = (float4*)bufs[p ^ 1];
                dst[tid] = nxt0;
                dst[tid + NTHREADS] = nxt1;
                dst[tid + 2 * NTHREADS] = nxt2;
                dst[tid + 3 * NTHREADS] = nxt3;
            }
            __syncthreads();
            p ^= 1;
        }

        // epilogue: all sAct reads finished at last sync
        #pragma unroll
        for (int i = 0; i < 8; i++) {
            #pragma unroll
            for (int j = 0; j < 4; j++) {
                int cp = (j < 2) ? (4 * lane + 2 * j) : (128 + 4 * lane + 2 * (j - 2));
                ull v = add2(acc[i][j], sB2[cp >> 1]);
                float lo, hi; unpack2(v, lo, hi);
                float2 st; st.x = tanha(lo); st.y = tanha(hi);
                *(float2*)&sAct[(row0 + i) * ASTR + cp] = st;
            }
        }
        __syncthreads();
    }

    // ---------- final layer: T_soft = c @ w4 + b4 ; outputs ----------
    {
        // load w4 transposed: sW4t[col][k], stride W4STR (spans bufA+part of bufB)
        float* sW4t = bufA;
        for (int idx = tid; idx < HID * NFORE; idx += NTHREADS) {
            int k = idx / NFORE, c = idx % NFORE;
            sW4t[c * W4STR + k] = w4[idx];
        }
        __syncthreads();

        // k-packed: acc pair holds (even-k, odd-k) partials for column `lane`
        ull accp[8];
        #pragma unroll
        for (int i = 0; i < 8; i++) accp[i] = 0ULL;

        for (int k = 0; k < HID; k += 4) {
            ulonglong2 wp = *(const ulonglong2*)&sW4t[lane * W4STR + k];
            #pragma unroll
            for (int i = 0; i < 8; i++) {
                ulonglong2 av = *(const ulonglong2*)&sAct[(row0 + i) * ASTR + k];
                accp[i] = fma2(av.x, wp.x, accp[i]);
                accp[i] = fma2(av.y, wp.y, accp[i]);
            }
        }

        if (lane < NFORE) {
            const float bb  = b4[lane];
            const float lam = sigmoidf_(p_lam[0]);
            #pragma unroll
            for (int i = 0; i < 8; i++) {
                float lo, hi; unpack2(accp[i], lo, hi);
                float ts = lo + hi + bb;
                int gr = gRow0 + row0 + i;
                float tp = sComb[(row0 + i) * CSTR + 24 + lane] + lam * ts;
                out[(size_t)gr * NFORE + lane] = tp;                           // T_pred
                out[(size_t)2 * B * NFORE + (size_t)gr * NFORE + lane] = ts;   // T_soft
            }
        }
    }
}

extern "C" void kernel_launch(void* const* d_in, const int* in_sizes, int n_in,
                              void* d_out, int out_size)
{
    const float* hist  = (const float*)d_in[0];
    const float* w1    = (const float*)d_in[1];
    const float* b1    = (const float*)d_in[2];
    const float* w2    = (const float*)d_in[3];
    const float* b2    = (const float*)d_in[4];
    const float* w3    = (const float*)d_in[5];
    const float* b3    = (const float*)d_in[6];
    const float* w4    = (const float*)d_in[7];
    const float* b4    = (const float*)d_in[8];
    const float* alpha = (const float*)d_in[9];
    const float* beta  = (const float*)d_in[10];
    const float* gamma = (const float*)d_in[11];
    const float* lamx  = (const float*)d_in[13];
    float* out = (float*)d_out;

    const int B = in_sizes[0] / NHIST;
    const int nblocks = (B + MT - 1) / MT;
    const size_t smem_bytes = (size_t)SMEM_FLOATS * sizeof(float);

    cudaFuncSetAttribute(axiom_fused_kernel,
                         cudaFuncAttributeMaxDynamicSharedMemorySize,
                         (int)smem_bytes);

    axiom_fused_kernel<<<nblocks, NTHREADS, smem_bytes>>>(
        hist, w1, b1, w2, b2, w3, b3, w4, b4,
        alpha, beta, gamma, lamx, out, B);
}

// round 4
// speedup vs baseline: 3.4286x; 2.8773x over previous
#include <cuda_runtime.h>
#include <cuda_bf16.h>
#include <math.h>
#include <cstdint>

#define NHIST 24
#define NFORE 20
#define MT    128
#define NTH   512
#define ASTR  264     // sAct row stride (bf16 elems)
#define WSTR  264     // W row stride (bf16 elems)
#define W4STR 40      // w4 row stride

// ---------------- prepped weights (bf16 hi/lo, padded) ----------------
// gW1: [split][64][264]            = 67584 B
// gW2/gW3: [tile(8)][split][32][264] = 270336 B
// gW4: [split][256][40]            = 40960 B
__device__ __align__(16) unsigned char gW1[67584];
__device__ __align__(16) unsigned char gW2[270336];
__device__ __align__(16) unsigned char gW3[270336];
__device__ __align__(16) unsigned char gW4[40960];

// ---------------- SMEM layout (bytes) ----------------
#define AHI_OFF  0
#define ALO_OFF  67584
#define WBUF_OFF 135168     // 2 x 33792 (ping-pong), or whole w1/w4
#define PHYS_OFF 202752     // 128*20 f32
#define BIAS_OFF 212992     // 768 f32 (b1,b2,b3)
#define B4_OFF   216064     // 32 f32 (padded)
#define SMEM_TOTAL 216192
#define WTILE_B  33792      // one (hi+lo) 32-k tile
#define WSPLIT_B 16896      // hi part of a tile

// ---------------- PTX helpers ----------------
__device__ __forceinline__ uint32_t smem_u32(const void* p) {
    uint32_t a;
    asm("{ .reg .u64 t; cvta.to.shared.u64 t, %1; cvt.u32.u64 %0, t; }" : "=r"(a) : "l"(p));
    return a;
}
__device__ __forceinline__ void ldm4(uint32_t r[4], uint32_t a) {
    asm volatile("ldmatrix.sync.aligned.m8n8.x4.shared.b16 {%0,%1,%2,%3}, [%4];"
                 : "=r"(r[0]), "=r"(r[1]), "=r"(r[2]), "=r"(r[3]) : "r"(a));
}
__device__ __forceinline__ void ldm4t(uint32_t r[4], uint32_t a) {
    asm volatile("ldmatrix.sync.aligned.m8n8.x4.trans.shared.b16 {%0,%1,%2,%3}, [%4];"
                 : "=r"(r[0]), "=r"(r[1]), "=r"(r[2]), "=r"(r[3]) : "r"(a));
}
__device__ __forceinline__ void ldm2t(uint32_t r[2], uint32_t a) {
    asm volatile("ldmatrix.sync.aligned.m8n8.x2.trans.shared.b16 {%0,%1}, [%2];"
                 : "=r"(r[0]), "=r"(r[1]) : "r"(a));
}
__device__ __forceinline__ void mmab(float c[4], const uint32_t a[4], const uint32_t b[2]) {
    asm volatile("mma.sync.aligned.m16n8k16.row.col.f32.bf16.bf16.f32 "
                 "{%0,%1,%2,%3}, {%4,%5,%6,%7}, {%8,%9}, {%0,%1,%2,%3};"
                 : "+f"(c[0]), "+f"(c[1]), "+f"(c[2]), "+f"(c[3])
                 : "r"(a[0]), "r"(a[1]), "r"(a[2]), "r"(a[3]), "r"(b[0]), "r"(b[1]));
}
__device__ __forceinline__ float tanha(float x) {
    float r; asm("tanh.approx.f32 %0, %1;" : "=f"(r) : "f"(x)); return r;
}
__device__ __forceinline__ uint32_t pack_bf(float lo, float hi) {
    __nv_bfloat162 t = __floats2bfloat162_rn(lo, hi);
    return *reinterpret_cast<uint32_t*>(&t);
}
__device__ __forceinline__ void split_bf(float x, uint32_t& hi16, uint32_t& lo16) {
    __nv_bfloat16 h = __float2bfloat16(x);
    float hf = __bfloat162float(h);
    __nv_bfloat16 l = __float2bfloat16(x - hf);
    hi16 = *(unsigned short*)&h;
    lo16 = *(unsigned short*)&l;
}

// ---------------- weight prep ----------------
__global__ void prep_kernel(const float* __restrict__ w1, const float* __restrict__ w2,
                            const float* __restrict__ w3, const float* __restrict__ w4)
{
    int idx = blockIdx.x * blockDim.x + threadIdx.x;
    int stride = gridDim.x * blockDim.x;
    // layer1: [64][264], real k<44, n<256
    for (int i = idx; i < 64 * 264; i += stride) {
        int k = i / 264, n = i % 264;
        float w = (k < 44 && n < 256) ? w1[k * 256 + n] : 0.0f;
        uint32_t h, l; split_bf(w, h, l);
        *(unsigned short*)(gW1 + (size_t)(k * 264 + n) * 2)         = (unsigned short)h;
        *(unsigned short*)(gW1 + 33792 + (size_t)(k * 264 + n) * 2) = (unsigned short)l;
    }
    // layers 2,3: [256][264], tiled by 32 k-rows
    for (int i = idx; i < 256 * 264; i += stride) {
        int k = i / 264, n = i % 264;
        int t = k >> 5, kr = k & 31;
        size_t off = (size_t)t * WTILE_B + (size_t)(kr * 264 + n) * 2;
        float wa = (n < 256) ? w2[k * 256 + n] : 0.0f;
        float wb = (n < 256) ? w3[k * 256 + n] : 0.0f;
        uint32_t h, l;
        split_bf(wa, h, l);
        *(unsigned short*)(gW2 + off)            = (unsigned short)h;
        *(unsigned short*)(gW2 + off + WSPLIT_B) = (unsigned short)l;
        split_bf(wb, h, l);
        *(unsigned short*)(gW3 + off)            = (unsigned short)h;
        *(unsigned short*)(gW3 + off + WSPLIT_B) = (unsigned short)l;
    }
    // layer4: [256][40], real n<20
    for (int i = idx; i < 256 * 40; i += stride) {
        int k = i / 40, n = i % 40;
        float w = (n < 20) ? w4[k * 20 + n] : 0.0f;
        uint32_t h, l; split_bf(w, h, l);
        *(unsigned short*)(gW4 + (size_t)(k * 40 + n) * 2)         = (unsigned short)h;
        *(unsigned short*)(gW4 + 20480 + (size_t)(k * 40 + n) * 2) = (unsigned short)l;
    }
}

// ---------------- gemm k16-step, full-width (n=64 per warp) ----------------
__device__ __forceinline__ void step_wide(uint32_t sb, int kA, uint32_t wHiOff, uint32_t wLoOff,
                                          int kW, int r0, int c0, int lane,
                                          float acc[2][8][4])
{
    const int lr = lane & 15, lh = lane >> 4;
    uint32_t ahi[2][4], alo[2][4];
    #pragma unroll
    for (int mi = 0; mi < 2; mi++) {
        uint32_t ao = (uint32_t)(((r0 + 16 * mi + lr) * ASTR + kA + 8 * lh) * 2);
        ldm4(ahi[mi], sb + AHI_OFF + ao);
        ldm4(alo[mi], sb + ALO_OFF + ao);
    }
    #pragma unroll
    for (int ni2 = 0; ni2 < 4; ni2++) {
        uint32_t wo = (uint32_t)(((kW + lr) * WSTR + c0 + 16 * ni2 + 8 * lh) * 2);
        uint32_t bh[4], bl[4];
        ldm4t(bh, sb + wHiOff + wo);
        ldm4t(bl, sb + wLoOff + wo);
        #pragma unroll
        for (int mi = 0; mi < 2; mi++) {
            mmab(acc[mi][2 * ni2],     ahi[mi], bh);
            mmab(acc[mi][2 * ni2 + 1], ahi[mi], bh + 2);
            mmab(acc[mi][2 * ni2],     alo[mi], bh);
            mmab(acc[mi][2 * ni2 + 1], alo[mi], bh + 2);
            mmab(acc[mi][2 * ni2],     ahi[mi], bl);
            mmab(acc[mi][2 * ni2 + 1], ahi[mi], bl + 2);
        }
    }
}

// epilogue: bias + tanh + bf16-split back into sAct
__device__ __forceinline__ void epilogue(unsigned char* dsm, const float* bl,
                                         float acc[2][8][4], int r0, int c0, int lane)
{
    const int qr = lane >> 2, qc = (lane & 3) * 2;
    #pragma unroll
    for (int mi = 0; mi < 2; mi++) {
        #pragma unroll
        for (int ni = 0; ni < 8; ni++) {
            int col = c0 + 8 * ni + qc;
            float2 bb = *(const float2*)&bl[col];
            int rA = r0 + 16 * mi + qr;
            #pragma unroll
            for (int h = 0; h < 2; h++) {
                int row = rA + 8 * h;
                float x0 = tanha(acc[mi][ni][2 * h]     + bb.x);
                float x1 = tanha(acc[mi][ni][2 * h + 1] + bb.y);
                __nv_bfloat16 h0 = __float2bfloat16(x0), h1 = __float2bfloat16(x1);
                float f0 = __bfloat162float(h0), f1 = __bfloat162float(h1);
                uint32_t hw = pack_bf(f0, f1);
                uint32_t lw = pack_bf(x0 - f0, x1 - f1);
                *(uint32_t*)(dsm + AHI_OFF + (size_t)(row * ASTR + col) * 2) = hw;
                *(uint32_t*)(dsm + ALO_OFF + (size_t)(row * ASTR + col) * 2) = lw;
            }
        }
    }
}

__global__ void __launch_bounds__(NTH, 1)
axiom_mma_kernel(const float* __restrict__ hist,
                 const float* __restrict__ b1, const float* __restrict__ b2,
                 const float* __restrict__ b3, const float* __restrict__ b4,
                 const float* __restrict__ p_alpha, const float* __restrict__ p_beta,
                 const float* __restrict__ p_gamma, const float* __restrict__ p_lam,
                 float* __restrict__ out, int B)
{
    extern __shared__ unsigned char dsm[];
    const uint32_t sb = smem_u32(dsm);
    float* sPhys = (float*)(dsm + PHYS_OFF);
    float* sBias = (float*)(dsm + BIAS_OFF);
    float* sB4   = (float*)(dsm + B4_OFF);

    const int tid  = threadIdx.x;
    const int lane = tid & 31;
    const int wrp  = tid >> 5;
    const int wm   = wrp & 3, wn = wrp >> 2;
    const int r0   = wm * 32, c0 = wn * 64;
    const int gRow0 = blockIdx.x * MT;

    // biases
    if (tid < 256) {
        sBias[tid]       = b1[tid];
        sBias[256 + tid] = b2[tid];
        sBias[512 + tid] = b3[tid];
    }
    if (tid < 32) sB4[tid] = (tid < NFORE) ? b4[tid] : 0.0f;

    // ---------- physics + build A1 (bf16 hi/lo) ----------
    if (tid < MT) {
        const float a = 1.0f / (1.0f + expf(-p_alpha[0]));
        const float b = 1.0f / (1.0f + expf(-p_beta[0]));
        const float g = fabsf(p_gamma[0]);
        float h[NHIST];
        const float4* hp = (const float4*)(hist + (size_t)(gRow0 + tid) * NHIST);
        #pragma unroll
        for (int i = 0; i < 6; i++) {
            float4 v = hp[i];
            h[4*i] = v.x; h[4*i+1] = v.y; h[4*i+2] = v.z; h[4*i+3] = v.w;
        }
        float ph[NFORE];
        float d0=h[18],d1=h[19],d2=h[20],d3=h[21],d4=h[22],d5=h[23];
        float T = d5;
        #pragma unroll
        for (int i = 0; i < NFORE; i++) {
            float Tn = T - a*T - b*d0 - g*(T*T*T);
            d0=d1; d1=d2; d2=d3; d3=d4; d4=d5; d5=Tn;
            ph[i] = Tn; T = Tn;
            sPhys[tid * NFORE + i] = Tn;
        }
        #pragma unroll
        for (int j = 0; j < 32; j++) {
            int k0 = 2*j, k1 = 2*j+1;
            float v0 = (k0 < 24) ? h[k0] : (k0 < 44) ? ph[k0-24] : 0.0f;
            float v1 = (k1 < 24) ? h[k1] : (k1 < 44) ? ph[k1-24] : 0.0f;
            __nv_bfloat16 h0 = __float2bfloat16(v0), h1 = __float2bfloat16(v1);
            float f0 = __bfloat162float(h0), f1 = __bfloat162float(h1);
            *(uint32_t*)(dsm + AHI_OFF + (size_t)(tid * ASTR + 2*j) * 2) = pack_bf(f0, f1);
            *(uint32_t*)(dsm + ALO_OFF + (size_t)(tid * ASTR + 2*j) * 2) = pack_bf(v0 - f0, v1 - f1);
        }
    }

    // copy whole w1 (67584 B) into wbuf
    for (int i = tid * 16; i < 67584; i += NTH * 16)
        *(uint4*)(dsm + WBUF_OFF + i) = *(const uint4*)(gW1 + i);
    __syncthreads();

    // T_physics out
    for (int i = tid; i < MT * NFORE; i += NTH)
        out[(size_t)B * NFORE + (size_t)gRow0 * NFORE + i] = sPhys[i];

    float acc[2][8][4];

    // ---------- layer 1: K=64 ----------
    #pragma unroll
    for (int mi = 0; mi < 2; mi++)
        #pragma unroll
        for (int ni = 0; ni < 8; ni++)
            #pragma unroll
            for (int q = 0; q < 4; q++) acc[mi][ni][q] = 0.0f;
    #pragma unroll
    for (int ks = 0; ks < 4; ks++)
        step_wide(sb, ks * 16, WBUF_OFF, WBUF_OFF + 33792, ks * 16, r0, c0, lane, acc);
    __syncthreads();
    epilogue(dsm, sBias, acc, r0, c0, lane);
    __syncthreads();

    // ---------- layers 2,3: K=256, ping-pong 32-k tiles ----------
    for (int l = 0; l < 2; l++) {
        const unsigned char* gw = l ? gW3 : gW2;
        // tile 0
        for (int i = tid * 16; i < WTILE_B; i += NTH * 16)
            *(uint4*)(dsm + WBUF_OFF + i) = *(const uint4*)(gw + i);
        __syncthreads();

        #pragma unroll
        for (int mi = 0; mi < 2; mi++)
            #pragma unroll
            for (int ni = 0; ni < 8; ni++)
                #pragma unroll
                for (int q = 0; q < 4; q++) acc[mi][ni][q] = 0.0f;

        int p = 0;
        for (int t = 0; t < 8; t++) {
            uint4 v[5];
            if (t < 7) {
                const unsigned char* src = gw + (size_t)(t + 1) * WTILE_B;
                #pragma unroll
                for (int s = 0; s < 5; s++) {
                    int off = tid * 16 + s * 8192;
                    if (off < WTILE_B) v[s] = *(const uint4*)(src + off);
                }
            }
            uint32_t wh = WBUF_OFF + p * WTILE_B;
            step_wide(sb, t * 32,      wh, wh + WSPLIT_B, 0,  r0, c0, lane, acc);
            step_wide(sb, t * 32 + 16, wh, wh + WSPLIT_B, 16, r0, c0, lane, acc);
            if (t < 7) {
                unsigned char* dst = dsm + WBUF_OFF + (p ^ 1) * WTILE_B;
                #pragma unroll
                for (int s = 0; s < 5; s++) {
                    int off = tid * 16 + s * 8192;
                    if (off < WTILE_B) *(uint4*)(dst + off) = v[s];
                }
            }
            __syncthreads();
            p ^= 1;
        }
        epilogue(dsm, sBias + 256 * (l + 1), acc, r0, c0, lane);
        __syncthreads();
    }

    // ---------- layer 4: N=32 (20 valid), K=256 ----------
    for (int i = tid * 16; i < 40960; i += NTH * 16)
        *(uint4*)(dsm + WBUF_OFF + i) = *(const uint4*)(gW4 + i);
    __syncthreads();

    {
        float a4[2][4];
        #pragma unroll
        for (int mi = 0; mi < 2; mi++)
            #pragma unroll
            for (int q = 0; q < 4; q++) a4[mi][q] = 0.0f;

        const int lr = lane & 15, lh = lane >> 4;
        const int c4 = wn * 8;
        for (int ks = 0; ks < 16; ks++) {
            int k = ks * 16;
            uint32_t ahi[2][4], alo[2][4];
            #pragma unroll
            for (int mi = 0; mi < 2; mi++) {
                uint32_t ao = (uint32_t)(((r0 + 16 * mi + lr) * ASTR + k + 8 * lh) * 2);
                ldm4(ahi[mi], sb + AHI_OFF + ao);
                ldm4(alo[mi], sb + ALO_OFF + ao);
            }
            uint32_t wo = (uint32_t)(((k + lr) * W4STR + c4) * 2);
            uint32_t bh[2], bl[2];
            ldm2t(bh, sb + WBUF_OFF + wo);
            ldm2t(bl, sb + WBUF_OFF + 20480 + wo);
            #pragma unroll
            for (int mi = 0; mi < 2; mi++) {
                mmab(a4[mi], ahi[mi], bh);
                mmab(a4[mi], alo[mi], bh);
                mmab(a4[mi], ahi[mi], bl);
            }
        }

        // final outputs
        const float lam = 1.0f / (1.0f + expf(-p_lam[0]));
        const int qr = lane >> 2, qc = (lane & 3) * 2;
        const int c = wn * 8 + qc;
        if (c < NFORE) {
            float2 bb = *(const float2*)&sB4[c];
            #pragma unroll
            for (int mi = 0; mi < 2; mi++) {
                #pragma unroll
                for (int h = 0; h < 2; h++) {
                    int row = r0 + 16 * mi + qr + 8 * h;
                    float ts0 = a4[mi][2*h]     + bb.x;
                    float ts1 = a4[mi][2*h + 1] + bb.y;
                    float tp0 = sPhys[row * NFORE + c]     + lam * ts0;
                    float tp1 = sPhys[row * NFORE + c + 1] + lam * ts1;
                    size_t go = (size_t)(gRow0 + row) * NFORE + c;
                    *(float2*)&out[go] = make_float2(tp0, tp1);
                    *(float2*)&out[(size_t)2 * B * NFORE + go] = make_float2(ts0, ts1);
                }
            }
        }
    }
}

// ---------------- launch ----------------
extern "C" void kernel_launch(void* const* d_in, const int* in_sizes, int n_in,
                              void* d_out, int out_size)
{
    const float* hist  = (const float*)d_in[0];
    const float* w1    = (const float*)d_in[1];
    const float* b1    = (const float*)d_in[2];
    const float* w2    = (const float*)d_in[3];
    const float* b2    = (const float*)d_in[4];
    const float* w3    = (const float*)d_in[5];
    const float* b3    = (const float*)d_in[6];
    const float* w4    = (const float*)d_in[7];
    const float* b4    = (const float*)d_in[8];
    const float* alpha = (const float*)d_in[9];
    const float* beta  = (const float*)d_in[10];
    const float* gamma = (const float*)d_in[11];
    const float* lamx  = (const float*)d_in[13];
    float* out = (float*)d_out;

    const int B = in_sizes[0] / NHIST;
    const int nblocks = B / MT;

    prep_kernel<<<132, 256>>>(w1, w2, w3, w4);

    cudaFuncSetAttribute(axiom_mma_kernel,
                         cudaFuncAttributeMaxDynamicSharedMemorySize, SMEM_TOTAL);
    axiom_mma_kernel<<<nblocks, NTH, SMEM_TOTAL>>>(
        hist, b1, b2, b3, b4, alpha, beta, gamma, lamx, out, B);
}

// round 5
// speedup vs baseline: 8.2571x; 2.4083x over previous
#include <cuda_runtime.h>
#include <cuda_fp16.h>
#include <math.h>
#include <cstdint>

#define NHIST 24
#define NFORE 20
#define MT    128
#define NTH   512
#define ASTR  264     // sAct row stride (fp16 elems)
#define WSTR  264
#define W4STR 40

// ---------------- prepped weights (fp16, padded) ----------------
__device__ __align__(16) unsigned char gW1[25344];    // [48][264]
__device__ __align__(16) unsigned char gW2[135168];   // [256][264]
__device__ __align__(16) unsigned char gW3[135168];
__device__ __align__(16) unsigned char gW4[20480];    // [256][40]

// ---------------- SMEM layout (bytes) ----------------
#define A_OFF    0          // 128*264*2 = 67584
#define WS_OFF   67584      // 3 slots x 33792 = 101376
#define SLOT_B   33792
#define PHYS_OFF 168960     // 128*20*4 = 10240
#define BIAS_OFF 179200     // 768*4
#define B4_OFF   182272     // 128
#define SMEM_TOTAL 182400

// ---------------- PTX helpers ----------------
__device__ __forceinline__ uint32_t smem_u32(const void* p) {
    uint32_t a;
    asm("{ .reg .u64 t; cvta.to.shared.u64 t, %1; cvt.u32.u64 %0, t; }" : "=r"(a) : "l"(p));
    return a;
}
__device__ __forceinline__ void ldm4(uint32_t r[4], uint32_t a) {
    asm volatile("ldmatrix.sync.aligned.m8n8.x4.shared.b16 {%0,%1,%2,%3}, [%4];"
                 : "=r"(r[0]), "=r"(r[1]), "=r"(r[2]), "=r"(r[3]) : "r"(a));
}
__device__ __forceinline__ void ldm4t(uint32_t r[4], uint32_t a) {
    asm volatile("ldmatrix.sync.aligned.m8n8.x4.trans.shared.b16 {%0,%1,%2,%3}, [%4];"
                 : "=r"(r[0]), "=r"(r[1]), "=r"(r[2]), "=r"(r[3]) : "r"(a));
}
__device__ __forceinline__ void ldm2t(uint32_t r[2], uint32_t a) {
    asm volatile("ldmatrix.sync.aligned.m8n8.x2.trans.shared.b16 {%0,%1}, [%2];"
                 : "=r"(r[0]), "=r"(r[1]) : "r"(a));
}
__device__ __forceinline__ void mmah(float c[4], const uint32_t a[4], const uint32_t b[2]) {
    asm volatile("mma.sync.aligned.m16n8k16.row.col.f32.f16.f16.f32 "
                 "{%0,%1,%2,%3}, {%4,%5,%6,%7}, {%8,%9}, {%0,%1,%2,%3};"
                 : "+f"(c[0]), "+f"(c[1]), "+f"(c[2]), "+f"(c[3])
                 : "r"(a[0]), "r"(a[1]), "r"(a[2]), "r"(a[3]), "r"(b[0]), "r"(b[1]));
}
__device__ __forceinline__ void cpa16(uint32_t s, const void* g) {
    asm volatile("cp.async.cg.shared.global [%0], [%1], 16;" :: "r"(s), "l"(g));
}
__device__ __forceinline__ void cpa_commit() {
    asm volatile("cp.async.commit_group;" ::: "memory");
}
template<int N> __device__ __forceinline__ void cpa_wait() {
    asm volatile("cp.async.wait_group %0;" :: "n"(N) : "memory");
}
__device__ __forceinline__ float tanha(float x) {
    float r; asm("tanh.approx.f32 %0, %1;" : "=f"(r) : "f"(x)); return r;
}
__device__ __forceinline__ uint32_t packh2(float lo, float hi) {
    __half2 t = __floats2half2_rn(lo, hi);
    return *reinterpret_cast<uint32_t*>(&t);
}

// ---------------- weight prep ----------------
__global__ void prep_kernel(const float* __restrict__ w1, const float* __restrict__ w2,
                            const float* __restrict__ w3, const float* __restrict__ w4)
{
    int idx = blockIdx.x * blockDim.x + threadIdx.x;
    int stride = gridDim.x * blockDim.x;
    for (int i = idx; i < 48 * 264; i += stride) {                  // W1 [48][264]
        int k = i / 264, n = i % 264;
        float w = (k < 44 && n < 256) ? w1[k * 256 + n] : 0.0f;
        *(__half*)(gW1 + (size_t)i * 2) = __float2half_rn(w);
    }
    for (int i = idx; i < 256 * 264; i += stride) {                 // W2, W3 [256][264]
        int k = i / 264, n = i % 264;
        float wa = (n < 256) ? w2[k * 256 + n] : 0.0f;
        float wb = (n < 256) ? w3[k * 256 + n] : 0.0f;
        *(__half*)(gW2 + (size_t)i * 2) = __float2half_rn(wa);
        *(__half*)(gW3 + (size_t)i * 2) = __float2half_rn(wb);
    }
    for (int i = idx; i < 256 * 40; i += stride) {                  // W4 [256][40]
        int k = i / 40, n = i % 40;
        float w = (n < 20) ? w4[k * 20 + n] : 0.0f;
        *(__half*)(gW4 + (size_t)i * 2) = __float2half_rn(w);
    }
}

// ---------------- async tile copy ----------------
__device__ __forceinline__ void prefetch_tile(uint32_t sdst, const unsigned char* gsrc,
                                              int bytes, int tid)
{
    for (int i = tid * 16; i < bytes; i += NTH * 16)
        cpa16(sdst + (uint32_t)i, gsrc + i);
    cpa_commit();
}

// ---------------- gemm k16-step, n=64 per warp, single fp16 term ----------------
__device__ __forceinline__ void step_wide(uint32_t sb, int kA, uint32_t wOff, int kW,
                                          int r0, int c0, int lane, float acc[2][8][4])
{
    const int lr = lane & 15, lh = lane >> 4;
    uint32_t a[2][4];
    #pragma unroll
    for (int mi = 0; mi < 2; mi++) {
        uint32_t ao = (uint32_t)(((r0 + 16 * mi + lr) * ASTR + kA + 8 * lh) * 2);
        ldm4(a[mi], sb + A_OFF + ao);
    }
    #pragma unroll
    for (int ni2 = 0; ni2 < 4; ni2++) {
        uint32_t wo = (uint32_t)(((kW + lr) * WSTR + c0 + 16 * ni2 + 8 * lh) * 2);
        uint32_t b[4];
        ldm4t(b, sb + wOff + wo);
        #pragma unroll
        for (int mi = 0; mi < 2; mi++) {
            mmah(acc[mi][2 * ni2],     a[mi], b);
            mmah(acc[mi][2 * ni2 + 1], a[mi], b + 2);
        }
    }
}

__device__ __forceinline__ void epilogue(unsigned char* dsm, const float* bl,
                                         float acc[2][8][4], int r0, int c0, int lane)
{
    const int qr = lane >> 2, qc = (lane & 3) * 2;
    #pragma unroll
    for (int mi = 0; mi < 2; mi++) {
        #pragma unroll
        for (int ni = 0; ni < 8; ni++) {
            int col = c0 + 8 * ni + qc;
            float2 bb = *(const float2*)&bl[col];
            #pragma unroll
            for (int h = 0; h < 2; h++) {
                int row = r0 + 16 * mi + qr + 8 * h;
                float x0 = tanha(acc[mi][ni][2 * h]     + bb.x);
                float x1 = tanha(acc[mi][ni][2 * h + 1] + bb.y);
                *(uint32_t*)(dsm + A_OFF + (size_t)(row * ASTR + col) * 2) = packh2(x0, x1);
            }
        }
    }
}

__global__ void __launch_bounds__(NTH, 1)
axiom_mma_kernel(const float* __restrict__ hist,
                 const float* __restrict__ b1, const float* __restrict__ b2,
                 const float* __restrict__ b3, const float* __restrict__ b4,
                 const float* __restrict__ p_alpha, const float* __restrict__ p_beta,
                 const float* __restrict__ p_gamma, const float* __restrict__ p_lam,
                 float* __restrict__ out, int B)
{
    extern __shared__ unsigned char dsm[];
    const uint32_t sb = smem_u32(dsm);
    float* sPhys = (float*)(dsm + PHYS_OFF);
    float* sBias = (float*)(dsm + BIAS_OFF);
    float* sB4   = (float*)(dsm + B4_OFF);

    const int tid  = threadIdx.x;
    const int lane = tid & 31;
    const int wrp  = tid >> 5;
    const int wm   = wrp & 3, wn = wrp >> 2;
    const int r0   = wm * 32, c0 = wn * 64;
    const int gRow0 = blockIdx.x * MT;

    // prefetch schedule (slots): W1->0, L2 t0..t3 -> 1,2,0,1, L3 t0..t3 -> 2,0,1,2, W4->0
    prefetch_tile(sb + WS_OFF + 0 * SLOT_B, gW1, 25344, tid);               // c1
    prefetch_tile(sb + WS_OFF + 1 * SLOT_B, gW2, SLOT_B, tid);              // c2
    prefetch_tile(sb + WS_OFF + 2 * SLOT_B, gW2 + SLOT_B, SLOT_B, tid);     // c3

    if (tid < 256) {
        sBias[tid]       = b1[tid];
        sBias[256 + tid] = b2[tid];
        sBias[512 + tid] = b3[tid];
    }
    if (tid < 32) sB4[tid] = (tid < NFORE) ? b4[tid] : 0.0f;

    // ---------- physics + build A1 (fp16) ----------
    if (tid < MT) {
        const float a = 1.0f / (1.0f + expf(-p_alpha[0]));
        const float b = 1.0f / (1.0f + expf(-p_beta[0]));
        const float g = fabsf(p_gamma[0]);
        float h[NHIST];
        const float4* hp = (const float4*)(hist + (size_t)(gRow0 + tid) * NHIST);
        #pragma unroll
        for (int i = 0; i < 6; i++) {
            float4 v = hp[i];
            h[4*i] = v.x; h[4*i+1] = v.y; h[4*i+2] = v.z; h[4*i+3] = v.w;
        }
        float ph[NFORE];
        float d0=h[18],d1=h[19],d2=h[20],d3=h[21],d4=h[22],d5=h[23];
        float T = d5;
        #pragma unroll
        for (int i = 0; i < NFORE; i++) {
            float Tn = T - a*T - b*d0 - g*(T*T*T);
            d0=d1; d1=d2; d2=d3; d3=d4; d4=d5; d5=Tn;
            ph[i] = Tn; T = Tn;
            sPhys[tid * NFORE + i] = Tn;
        }
        #pragma unroll
        for (int j = 0; j < 24; j++) {          // cols 0..47
            int k0 = 2*j, k1 = 2*j+1;
            float v0 = (k0 < 24) ? h[k0] : (k0 < 44) ? ph[k0-24] : 0.0f;
            float v1 = (k1 < 24) ? h[k1] : (k1 < 44) ? ph[k1-24] : 0.0f;
            *(uint32_t*)(dsm + A_OFF + (size_t)(tid * ASTR + 2*j) * 2) = packh2(v0, v1);
        }
    }

    cpa_wait<2>();      // W1 resident
    __syncthreads();

    // T_physics out
    for (int i = tid; i < MT * NFORE; i += NTH)
        out[(size_t)B * NFORE + (size_t)gRow0 * NFORE + i] = sPhys[i];

    float acc[2][8][4];
    #define ZERO_ACC() { _Pragma("unroll") for (int mi = 0; mi < 2; mi++) \
        _Pragma("unroll") for (int ni = 0; ni < 8; ni++) \
        _Pragma("unroll") for (int q = 0; q < 4; q++) acc[mi][ni][q] = 0.0f; }

    // ---------- layer 1: K=48 ----------
    ZERO_ACC();
    #pragma unroll
    for (int ks = 0; ks < 3; ks++)
        step_wide(sb, ks * 16, WS_OFF + 0 * SLOT_B, ks * 16, r0, c0, lane, acc);
    __syncthreads();
    epilogue(dsm, sBias, acc, r0, c0, lane);
    __syncthreads();

    // ---------- layer 2: 4 tiles (slots 1,2,0,1), prefetch t2,t3,L3t0,L3t1 ----------
    {
        ZERO_ACC();
        static const int slot[4]  = {1, 2, 0, 1};
        static const int pslot[4] = {0, 1, 2, 0};
        const unsigned char* pf[4] = {gW2 + 2*SLOT_B, gW2 + 3*SLOT_B, gW3, gW3 + SLOT_B};
        #pragma unroll
        for (int t = 0; t < 4; t++) {
            cpa_wait<1>();
            __syncthreads();
            prefetch_tile(sb + WS_OFF + pslot[t] * SLOT_B, pf[t], SLOT_B, tid);
            uint32_t wOff = WS_OFF + (uint32_t)slot[t] * SLOT_B;
            #pragma unroll
            for (int ks = 0; ks < 4; ks++)
                step_wide(sb, t * 64 + ks * 16, wOff, ks * 16, r0, c0, lane, acc);
        }
        __syncthreads();
        epilogue(dsm, sBias + 256, acc, r0, c0, lane);
        __syncthreads();
    }

    // ---------- layer 3: 4 tiles (slots 2,0,1,2), prefetch L3t2,L3t3,W4 ----------
    {
        ZERO_ACC();
        static const int slot[4] = {2, 0, 1, 2};
        #pragma unroll
        for (int t = 0; t < 4; t++) {
            cpa_wait<1>();
            __syncthreads();
            if (t == 0) prefetch_tile(sb + WS_OFF + 1 * SLOT_B, gW3 + 2*SLOT_B, SLOT_B, tid);
            if (t == 1) prefetch_tile(sb + WS_OFF + 2 * SLOT_B, gW3 + 3*SLOT_B, SLOT_B, tid);
            if (t == 2) prefetch_tile(sb + WS_OFF + 0 * SLOT_B, gW4, 20480, tid);
            uint32_t wOff = WS_OFF + (uint32_t)slot[t] * SLOT_B;
            #pragma unroll
            for (int ks = 0; ks < 4; ks++)
                step_wide(sb, t * 64 + ks * 16, wOff, ks * 16, r0, c0, lane, acc);
        }
        __syncthreads();
        epilogue(dsm, sBias + 512, acc, r0, c0, lane);
        __syncthreads();
    }

    // ---------- layer 4: N=32 (20 valid), K=256, W4 in slot 0 ----------
    cpa_wait<0>();
    __syncthreads();
    {
        float a4[2][4];
        #pragma unroll
        for (int mi = 0; mi < 2; mi++)
            #pragma unroll
            for (int q = 0; q < 4; q++) a4[mi][q] = 0.0f;

        const int lr = lane & 15, lh = lane >> 4;
        const int c4 = wn * 8;
        #pragma unroll 4
        for (int ks = 0; ks < 16; ks++) {
            int k = ks * 16;
            uint32_t a[2][4];
            #pragma unroll
            for (int mi = 0; mi < 2; mi++) {
                uint32_t ao = (uint32_t)(((r0 + 16 * mi + lr) * ASTR + k + 8 * lh) * 2);
                ldm4(a[mi], sb + A_OFF + ao);
            }
            uint32_t wo = (uint32_t)(((k + lr) * W4STR + c4) * 2);
            uint32_t b[2];
            ldm2t(b, sb + WS_OFF + wo);
            #pragma unroll
            for (int mi = 0; mi < 2; mi++) mmah(a4[mi], a[mi], b);
        }

        const float lam = 1.0f / (1.0f + expf(-p_lam[0]));
        const int qr = lane >> 2, qc = (lane & 3) * 2;
        const int c = wn * 8 + qc;
        if (c < NFORE) {
            float2 bb = *(const float2*)&sB4[c];
            #pragma unroll
            for (int mi = 0; mi < 2; mi++) {
                #pragma unroll
                for (int h = 0; h < 2; h++) {
                    int row = r0 + 16 * mi + qr + 8 * h;
                    float ts0 = a4[mi][2*h]     + bb.x;
                    float ts1 = a4[mi][2*h + 1] + bb.y;
                    float tp0 = sPhys[row * NFORE + c]     + lam * ts0;
                    float tp1 = sPhys[row * NFORE + c + 1] + lam * ts1;
                    size_t go = (size_t)(gRow0 + row) * NFORE + c;
                    *(float2*)&out[go] = make_float2(tp0, tp1);
                    *(float2*)&out[(size_t)2 * B * NFORE + go] = make_float2(ts0, ts1);
                }
            }
        }
    }
}

// ---------------- launch ----------------
extern "C" void kernel_launch(void* const* d_in, const int* in_sizes, int n_in,
                              void* d_out, int out_size)
{
    const float* hist  = (const float*)d_in[0];
    const float* w1    = (const float*)d_in[1];
    const float* b1    = (const float*)d_in[2];
    const float* w2    = (const float*)d_in[3];
    const float* b2    = (const float*)d_in[4];
    const float* w3    = (const float*)d_in[5];
    const float* b3    = (const float*)d_in[6];
    const float* w4    = (const float*)d_in[7];
    const float* b4    = (const float*)d_in[8];
    const float* alpha = (const float*)d_in[9];
    const float* beta  = (const float*)d_in[10];
    const float* gamma = (const float*)d_in[11];
    const float* lamx  = (const float*)d_in[13];
    float* out = (float*)d_out;

    const int B = in_sizes[0] / NHIST;
    const int nblocks = B / MT;

    prep_kernel<<<132, 256>>>(w1, w2, w3, w4);

    cudaFuncSetAttribute(axiom_mma_kernel,
                         cudaFuncAttributeMaxDynamicSharedMemorySize, SMEM_TOTAL);
    axiom_mma_kernel<<<nblocks, NTH, SMEM_TOTAL>>>(
        hist, b1, b2, b3, b4, alpha, beta, gamma, lamx, out, B);
}

// round 6
// speedup vs baseline: 9.9351x; 1.2032x over previous
#include <cuda_runtime.h>
#include <cuda_fp16.h>
#include <math.h>
#include <cstdint>

#define NHIST 24
#define NFORE 20
#define MT    64
#define NTH   256
#define ASTR  264     // sAct row stride (fp16 elems)
#define WSTR  264
#define W4STR 40

// ---------------- prepped weights (fp16, padded) ----------------
__device__ __align__(16) unsigned char gW1[25344];    // [48][264]
__device__ __align__(16) unsigned char gW2[135168];   // [256][264]
__device__ __align__(16) unsigned char gW3[135168];
__device__ __align__(16) unsigned char gW4[20480];    // [256][40]

// ---------------- SMEM layout (bytes) ----------------
#define A_OFF    0          // 64*264*2 = 33792
#define WS_OFF   33792      // 2 slots x 33792
#define SLOT_B   33792
#define PHYS_OFF 101376     // 64*20*4 = 5120
#define BIAS_OFF 106496     // 768*4 = 3072
#define B4_OFF   109568     // 128
#define SMEM_TOTAL 109696

// ---------------- PTX helpers ----------------
__device__ __forceinline__ uint32_t smem_u32(const void* p) {
    uint32_t a;
    asm("{ .reg .u64 t; cvta.to.shared.u64 t, %1; cvt.u32.u64 %0, t; }" : "=r"(a) : "l"(p));
    return a;
}
__device__ __forceinline__ void ldm4(uint32_t r[4], uint32_t a) {
    asm volatile("ldmatrix.sync.aligned.m8n8.x4.shared.b16 {%0,%1,%2,%3}, [%4];"
                 : "=r"(r[0]), "=r"(r[1]), "=r"(r[2]), "=r"(r[3]) : "r"(a));
}
__device__ __forceinline__ void ldm4t(uint32_t r[4], uint32_t a) {
    asm volatile("ldmatrix.sync.aligned.m8n8.x4.trans.shared.b16 {%0,%1,%2,%3}, [%4];"
                 : "=r"(r[0]), "=r"(r[1]), "=r"(r[2]), "=r"(r[3]) : "r"(a));
}
__device__ __forceinline__ void ldm2t(uint32_t r[2], uint32_t a) {
    asm volatile("ldmatrix.sync.aligned.m8n8.x2.trans.shared.b16 {%0,%1}, [%2];"
                 : "=r"(r[0]), "=r"(r[1]) : "r"(a));
}
__device__ __forceinline__ void mmah(float c[4], const uint32_t a[4], const uint32_t b[2]) {
    asm volatile("mma.sync.aligned.m16n8k16.row.col.f32.f16.f16.f32 "
                 "{%0,%1,%2,%3}, {%4,%5,%6,%7}, {%8,%9}, {%0,%1,%2,%3};"
                 : "+f"(c[0]), "+f"(c[1]), "+f"(c[2]), "+f"(c[3])
                 : "r"(a[0]), "r"(a[1]), "r"(a[2]), "r"(a[3]), "r"(b[0]), "r"(b[1]));
}
__device__ __forceinline__ void cpa16(uint32_t s, const void* g) {
    asm volatile("cp.async.cg.shared.global [%0], [%1], 16;" :: "r"(s), "l"(g));
}
__device__ __forceinline__ void cpa_commit() {
    asm volatile("cp.async.commit_group;" ::: "memory");
}
template<int N> __device__ __forceinline__ void cpa_wait() {
    asm volatile("cp.async.wait_group %0;" :: "n"(N) : "memory");
}
__device__ __forceinline__ float tanha(float x) {
    float r; asm("tanh.approx.f32 %0, %1;" : "=f"(r) : "f"(x)); return r;
}
__device__ __forceinline__ uint32_t packh2(float lo, float hi) {
    __half2 t = __floats2half2_rn(lo, hi);
    return *reinterpret_cast<uint32_t*>(&t);
}

// ---------------- weight prep ----------------
__global__ void prep_kernel(const float* __restrict__ w1, const float* __restrict__ w2,
                            const float* __restrict__ w3, const float* __restrict__ w4)
{
    int idx = blockIdx.x * blockDim.x + threadIdx.x;
    int stride = gridDim.x * blockDim.x;
    for (int i = idx; i < 48 * 264; i += stride) {
        int k = i / 264, n = i % 264;
        float w = (k < 44 && n < 256) ? w1[k * 256 + n] : 0.0f;
        *(__half*)(gW1 + (size_t)i * 2) = __float2half_rn(w);
    }
    for (int i = idx; i < 256 * 264; i += stride) {
        int k = i / 264, n = i % 264;
        float wa = (n < 256) ? w2[k * 256 + n] : 0.0f;
        float wb = (n < 256) ? w3[k * 256 + n] : 0.0f;
        *(__half*)(gW2 + (size_t)i * 2) = __float2half_rn(wa);
        *(__half*)(gW3 + (size_t)i * 2) = __float2half_rn(wb);
    }
    for (int i = idx; i < 256 * 40; i += stride) {
        int k = i / 40, n = i % 40;
        float w = (n < 20) ? w4[k * 20 + n] : 0.0f;
        *(__half*)(gW4 + (size_t)i * 2) = __float2half_rn(w);
    }
}

__device__ __forceinline__ void prefetch_tile(uint32_t sdst, const unsigned char* gsrc,
                                              int bytes, int tid)
{
    for (int i = tid * 16; i < bytes; i += NTH * 16)
        cpa16(sdst + (uint32_t)i, gsrc + i);
    cpa_commit();
}

// ---------------- gemm k16-step, n=64 per warp ----------------
__device__ __forceinline__ void step_wide(uint32_t sb, int kA, uint32_t wOff, int kW,
                                          int r0, int c0, int lane, float acc[2][8][4])
{
    const int lr = lane & 15, lh = lane >> 4;
    uint32_t a[2][4];
    #pragma unroll
    for (int mi = 0; mi < 2; mi++) {
        uint32_t ao = (uint32_t)(((r0 + 16 * mi + lr) * ASTR + kA + 8 * lh) * 2);
        ldm4(a[mi], sb + A_OFF + ao);
    }
    #pragma unroll
    for (int ni2 = 0; ni2 < 4; ni2++) {
        uint32_t wo = (uint32_t)(((kW + lr) * WSTR + c0 + 16 * ni2 + 8 * lh) * 2);
        uint32_t b[4];
        ldm4t(b, sb + wOff + wo);
        #pragma unroll
        for (int mi = 0; mi < 2; mi++) {
            mmah(acc[mi][2 * ni2],     a[mi], b);
            mmah(acc[mi][2 * ni2 + 1], a[mi], b + 2);
        }
    }
}

__device__ __forceinline__ void epilogue(unsigned char* dsm, const float* bl,
                                         float acc[2][8][4], int r0, int c0, int lane)
{
    const int qr = lane >> 2, qc = (lane & 3) * 2;
    #pragma unroll
    for (int mi = 0; mi < 2; mi++) {
        #pragma unroll
        for (int ni = 0; ni < 8; ni++) {
            int col = c0 + 8 * ni + qc;
            float2 bb = *(const float2*)&bl[col];
            #pragma unroll
            for (int h = 0; h < 2; h++) {
                int row = r0 + 16 * mi + qr + 8 * h;
                float x0 = tanha(acc[mi][ni][2 * h]     + bb.x);
                float x1 = tanha(acc[mi][ni][2 * h + 1] + bb.y);
                *(uint32_t*)(dsm + A_OFF + (size_t)(row * ASTR + col) * 2) = packh2(x0, x1);
            }
        }
    }
}

#define ZERO_ACC(acc) { _Pragma("unroll") for (int mi = 0; mi < 2; mi++) \
    _Pragma("unroll") for (int ni = 0; ni < 8; ni++) \
    _Pragma("unroll") for (int q = 0; q < 4; q++) acc[mi][ni][q] = 0.0f; }

__global__ void __launch_bounds__(NTH, 2)
axiom_mma_kernel(const float* __restrict__ hist,
                 const float* __restrict__ b1, const float* __restrict__ b2,
                 const float* __restrict__ b3, const float* __restrict__ b4,
                 const float* __restrict__ p_alpha, const float* __restrict__ p_beta,
                 const float* __restrict__ p_gamma, const float* __restrict__ p_lam,
                 float* __restrict__ out, int B)
{
    extern __shared__ unsigned char dsm[];
    const uint32_t sb = smem_u32(dsm);
    float* sPhys = (float*)(dsm + PHYS_OFF);
    float* sBias = (float*)(dsm + BIAS_OFF);
    float* sB4   = (float*)(dsm + B4_OFF);

    const int tid  = threadIdx.x;
    const int lane = tid & 31;
    const int wrp  = tid >> 5;
    const int wm   = wrp & 1, wn = wrp >> 1;
    const int r0   = wm * 32, c0 = wn * 64;
    const int gRow0 = blockIdx.x * MT;

    // pipeline seq: 0:W1(s0) 1:L2t0(s1) 2:L2t1(s0) 3:L2t2(s1) 4:L2t3(s0)
    //               5:L3t0(s1) 6:L3t1(s0) 7:L3t2(s1) 8:L3t3(s0) 9:W4(s1)
    prefetch_tile(sb + WS_OFF + 0 * SLOT_B, gW1, 25344, tid);
    prefetch_tile(sb + WS_OFF + 1 * SLOT_B, gW2, SLOT_B, tid);

    if (tid < 256) {
        sBias[tid]       = b1[tid];
        sBias[256 + tid] = b2[tid];
        sBias[512 + tid] = b3[tid];
    }
    if (tid < 32) sB4[tid] = (tid < NFORE) ? b4[tid] : 0.0f;

    // ---------- physics + build A1 (fp16) ----------
    if (tid < MT) {
        const float a = 1.0f / (1.0f + expf(-p_alpha[0]));
        const float b = 1.0f / (1.0f + expf(-p_beta[0]));
        const float g = fabsf(p_gamma[0]);
        float h[NHIST];
        const float4* hp = (const float4*)(hist + (size_t)(gRow0 + tid) * NHIST);
        #pragma unroll
        for (int i = 0; i < 6; i++) {
            float4 v = hp[i];
            h[4*i] = v.x; h[4*i+1] = v.y; h[4*i+2] = v.z; h[4*i+3] = v.w;
        }
        float ph[NFORE];
        float d0=h[18],d1=h[19],d2=h[20],d3=h[21],d4=h[22],d5=h[23];
        float T = d5;
        #pragma unroll
        for (int i = 0; i < NFORE; i++) {
            float Tn = T - a*T - b*d0 - g*(T*T*T);
            d0=d1; d1=d2; d2=d3; d3=d4; d4=d5; d5=Tn;
            ph[i] = Tn; T = Tn;
            sPhys[tid * NFORE + i] = Tn;
        }
        #pragma unroll
        for (int j = 0; j < 24; j++) {
            int k0 = 2*j, k1 = 2*j+1;
            float v0 = (k0 < 24) ? h[k0] : (k0 < 44) ? ph[k0-24] : 0.0f;
            float v1 = (k1 < 24) ? h[k1] : (k1 < 44) ? ph[k1-24] : 0.0f;
            *(uint32_t*)(dsm + A_OFF + (size_t)(tid * ASTR + 2*j) * 2) = packh2(v0, v1);
        }
    }

    float acc[2][8][4];

    // ---------- seq 0: layer 1, K=48, slot 0 ----------
    cpa_wait<1>();
    __syncthreads();

    // T_physics out
    for (int i = tid; i < MT * NFORE; i += NTH)
        out[(size_t)B * NFORE + (size_t)gRow0 * NFORE + i] = sPhys[i];

    ZERO_ACC(acc);
    #pragma unroll
    for (int ks = 0; ks < 3; ks++)
        step_wide(sb, ks * 16, WS_OFF + 0 * SLOT_B, ks * 16, r0, c0, lane, acc);
    __syncthreads();                      // done reading A1 + slot0
    prefetch_tile(sb + WS_OFF + 0 * SLOT_B, gW2 + SLOT_B, SLOT_B, tid);   // seq2
    epilogue(dsm, sBias, acc, r0, c0, lane);
    __syncthreads();                      // A2 visible

    // ---------- seq 1..4: layer 2, tiles 0..3 ----------
    {
        ZERO_ACC(acc);
        const unsigned char* pf[4] = {gW2 + 2*SLOT_B, gW2 + 3*SLOT_B, gW3, gW3 + SLOT_B}; // seq3..6
        #pragma unroll
        for (int t = 0; t < 4; t++) {
            const int s = (t + 1) & 1;    // seq (t+1) slot
            cpa_wait<1>();
            __syncthreads();
            #pragma unroll
            for (int ks = 0; ks < 4; ks++)
                step_wide(sb, t * 64 + ks * 16, WS_OFF + (uint32_t)s * SLOT_B, ks * 16,
                          r0, c0, lane, acc);
            __syncthreads();              // slot s consumed
            prefetch_tile(sb + WS_OFF + (uint32_t)s * SLOT_B, pf[t], SLOT_B, tid);
        }
        epilogue(dsm, sBias + 256, acc, r0, c0, lane);
        __syncthreads();
    }

    // ---------- seq 5..8: layer 3, tiles 0..3 ----------
    {
        ZERO_ACC(acc);
        const unsigned char* pf[4] = {gW3 + 2*SLOT_B, gW3 + 3*SLOT_B, gW4, 0}; // seq7,8,9
        const int pfb[4] = {SLOT_B, SLOT_B, 20480, 0};
        #pragma unroll
        for (int t = 0; t < 4; t++) {
            const int s = (t + 5) & 1;
            cpa_wait<1>();
            __syncthreads();
            #pragma unroll
            for (int ks = 0; ks < 4; ks++)
                step_wide(sb, t * 64 + ks * 16, WS_OFF + (uint32_t)s * SLOT_B, ks * 16,
                          r0, c0, lane, acc);
            __syncthreads();
            if (t < 3) prefetch_tile(sb + WS_OFF + (uint32_t)s * SLOT_B, pf[t], pfb[t], tid);
        }
        epilogue(dsm, sBias + 512, acc, r0, c0, lane);
        __syncthreads();
    }

    // ---------- seq 9: layer 4, N=32 (20 valid), K=256, slot 1 ----------
    cpa_wait<0>();
    __syncthreads();
    {
        float a4[2][4];
        #pragma unroll
        for (int mi = 0; mi < 2; mi++)
            #pragma unroll
            for (int q = 0; q < 4; q++) a4[mi][q] = 0.0f;

        const int lr = lane & 15, lh = lane >> 4;
        const int c4 = wn * 8;
        const uint32_t w4base = sb + WS_OFF + 1 * SLOT_B;
        #pragma unroll 4
        for (int ks = 0; ks < 16; ks++) {
            int k = ks * 16;
            uint32_t a[2][4];
            #pragma unroll
            for (int mi = 0; mi < 2; mi++) {
                uint32_t ao = (uint32_t)(((r0 + 16 * mi + lr) * ASTR + k + 8 * lh) * 2);
                ldm4(a[mi], sb + A_OFF + ao);
            }
            uint32_t wo = (uint32_t)(((k + lr) * W4STR + c4) * 2);
            uint32_t b[2];
            ldm2t(b, w4base + wo);
            #pragma unroll
            for (int mi = 0; mi < 2; mi++) mmah(a4[mi], a[mi], b);
        }

        const float lam = 1.0f / (1.0f + expf(-p_lam[0]));
        const int qr = lane >> 2, qc = (lane & 3) * 2;
        const int c = wn * 8 + qc;
        if (c < NFORE) {
            float2 bb = *(const float2*)&sB4[c];
            #pragma unroll
            for (int mi = 0; mi < 2; mi++) {
                #pragma unroll
                for (int h = 0; h < 2; h++) {
                    int row = r0 + 16 * mi + qr + 8 * h;
                    float ts0 = a4[mi][2*h]     + bb.x;
                    float ts1 = a4[mi][2*h + 1] + bb.y;
                    float tp0 = sPhys[row * NFORE + c]     + lam * ts0;
                    float tp1 = sPhys[row * NFORE + c + 1] + lam * ts1;
                    size_t go = (size_t)(gRow0 + row) * NFORE + c;
                    *(float2*)&out[go] = make_float2(tp0, tp1);
                    *(float2*)&out[(size_t)2 * B * NFORE + go] = make_float2(ts0, ts1);
                }
            }
        }
    }
}

// ---------------- launch ----------------
extern "C" void kernel_launch(void* const* d_in, const int* in_sizes, int n_in,
                              void* d_out, int out_size)
{
    const float* hist  = (const float*)d_in[0];
    const float* w1    = (const float*)d_in[1];
    const float* b1    = (const float*)d_in[2];
    const float* w2    = (const float*)d_in[3];
    const float* b2    = (const float*)d_in[4];
    const float* w3    = (const float*)d_in[5];
    const float* b3    = (const float*)d_in[6];
    const float* w4    = (const float*)d_in[7];
    const float* b4    = (const float*)d_in[8];
    const float* alpha = (const float*)d_in[9];
    const float* beta  = (const float*)d_in[10];
    const float* gamma = (const float*)d_in[11];
    const float* lamx  = (const float*)d_in[13];
    float* out = (float*)d_out;

    const int B = in_sizes[0] / NHIST;
    const int nblocks = B / MT;

    prep_kernel<<<132, 256>>>(w1, w2, w3, w4);

    cudaFuncSetAttribute(axiom_mma_kernel,
                         cudaFuncAttributeMaxDynamicSharedMemorySize, SMEM_TOTAL);
    axiom_mma_kernel<<<nblocks, NTH, SMEM_TOTAL>>>(
        hist, b1, b2, b3, b4, alpha, beta, gamma, lamx, out, B);
}